// round 1
// baseline (speedup 1.0000x reference)
#include <cuda_runtime.h>

#define B_  64
#define L_  200
#define NS_ 1000
#define D_  128
#define M_  50
#define BL_ (B_*L_)
#define ROWS 32
#define WSTR 64   // padded per-row stride of w (slots 50..63 are zero)

// -------- scratch (device globals; no allocation allowed) --------
__device__ float g_w[BL_*WSTR];     // softmax weights, padded
__device__ float g_e[BL_*D_];       // sigmoid erase
__device__ float g_a[BL_*D_];       // tanh add
__device__ float g_read[BL_*D_];    // read vectors

__device__ __forceinline__ float fsigmoid(float x){ return 1.f/(1.f+__expf(-x)); }
__device__ __forceinline__ float ftanh(float x){ float y; asm("tanh.approx.f32 %0, %1;":"=f"(y):"f"(x)); return y; }

// =====================================================================
// Kernel 1: per-row precompute of w (softmax(k·Mk^T)), e, a
// 400 blocks x 256 threads, 32 rows/block
// smem: kx[32][128] vx[32][128] MkT[128][65] eWT[128][132] aWT[128][132]
// =====================================================================
extern "C" __global__ void __launch_bounds__(256)
k1_precompute(const int* __restrict__ skills, const int* __restrict__ responses,
              const float* __restrict__ k_emb, const float* __restrict__ v_emb,
              const float* __restrict__ Mk,
              const float* __restrict__ e_W, const float* __restrict__ e_b,
              const float* __restrict__ a_W, const float* __restrict__ a_b)
{
    extern __shared__ float sm[];
    float* kx  = sm;                 // 32*128 = 4096
    float* vx  = kx  + ROWS*D_;      // 4096
    float* MkT = vx  + ROWS*D_;      // 128*65 = 8320
    float* eWT = MkT + D_*65;        // 128*132 = 16896
    float* aWT = eWT + D_*132;       // 16896
    __shared__ int s_idx[2*ROWS];

    const int tid  = threadIdx.x;
    const int row0 = blockIdx.x * ROWS;

    if (tid < ROWS) {
        int sk = skills[row0 + tid];
        int r  = responses[row0 + tid];
        int mr = (r > -1) ? r : 0;
        s_idx[tid]        = sk;
        s_idx[ROWS + tid] = sk + NS_ * mr;
    }
    // transposed Mk  (m pad 50..63 -> 0)
    for (int i = tid; i < M_*D_; i += 256) {
        int m = i >> 7, k = i & 127;
        MkT[k*65 + m] = Mk[i];
    }
    for (int i = tid; i < D_*14; i += 256) {
        int k = i / 14, m = 50 + (i % 14);
        MkT[k*65 + m] = 0.f;
    }
    // transposed weights
    for (int i = tid; i < D_*D_; i += 256) {
        int d = i >> 7, k = i & 127;
        eWT[k*132 + d] = e_W[i];
        aWT[k*132 + d] = a_W[i];
    }
    __syncthreads();
    // gather k / v rows (float4)
    {
        float4* kx4 = (float4*)kx; float4* vx4 = (float4*)vx;
        const float4* ke4 = (const float4*)k_emb;
        const float4* ve4 = (const float4*)v_emb;
        for (int u = tid; u < ROWS*32; u += 256) {
            int r = u >> 5, c = u & 31;
            kx4[r*32 + c] = ke4[s_idx[r]*32 + c];
            vx4[r*32 + c] = ve4[s_idx[ROWS + r]*32 + c];
        }
    }
    __syncthreads();

    const int tx = tid & 31, ty = tid >> 5;
    const int r0 = ty * 4;       // 4 rows per thread
    const int c0 = tx * 4;       // 4 cols per thread (GEMM)

    // ---------------- logits + softmax -> g_w ----------------
    {
        const int m0 = tx, m1 = tx + 32;
        float acc[4][2] = {};
        const float4* kx4 = (const float4*)kx;
        #pragma unroll 4
        for (int k4 = 0; k4 < 32; k4++) {
            float4 kr[4];
            #pragma unroll
            for (int i = 0; i < 4; i++) kr[i] = kx4[(r0+i)*32 + k4];
            #pragma unroll
            for (int s = 0; s < 4; s++) {
                int k = 4*k4 + s;
                float mv0 = MkT[k*65 + m0];
                float mv1 = MkT[k*65 + m1];
                #pragma unroll
                for (int i = 0; i < 4; i++) {
                    float kv = ((float*)&kr[i])[s];
                    acc[i][0] = fmaf(kv, mv0, acc[i][0]);
                    acc[i][1] = fmaf(kv, mv1, acc[i][1]);
                }
            }
        }
        #pragma unroll
        for (int i = 0; i < 4; i++) {
            float v0 = acc[i][0];
            float v1 = (m1 < M_) ? acc[i][1] : -1e30f;
            float mx = fmaxf(v0, v1);
            #pragma unroll
            for (int o = 16; o >= 1; o >>= 1) mx = fmaxf(mx, __shfl_xor_sync(0xffffffffu, mx, o));
            float e0 = __expf(v0 - mx);
            float e1 = (m1 < M_) ? __expf(v1 - mx) : 0.f;
            float s = e0 + e1;
            #pragma unroll
            for (int o = 16; o >= 1; o >>= 1) s += __shfl_xor_sync(0xffffffffu, s, o);
            float inv = __frcp_rn(s);
            int row = row0 + r0 + i;
            g_w[row*WSTR + m0] = e0 * inv;
            g_w[row*WSTR + m1] = e1 * inv;   // e1==0 in pad region -> writes the zero pad
        }
    }

    // ---------------- e/a GEMM ----------------
    {
        float ae[4][4] = {}, aa[4][4] = {};
        const float4* vx4 = (const float4*)vx;
        #pragma unroll 4
        for (int k4 = 0; k4 < 32; k4++) {
            float4 vr[4];
            #pragma unroll
            for (int i = 0; i < 4; i++) vr[i] = vx4[(r0+i)*32 + k4];
            #pragma unroll
            for (int s = 0; s < 4; s++) {
                int k = 4*k4 + s;
                float4 we = *(const float4*)&eWT[k*132 + c0];
                float4 wa = *(const float4*)&aWT[k*132 + c0];
                #pragma unroll
                for (int i = 0; i < 4; i++) {
                    float vv = ((float*)&vr[i])[s];
                    ae[i][0] = fmaf(vv, we.x, ae[i][0]);
                    ae[i][1] = fmaf(vv, we.y, ae[i][1]);
                    ae[i][2] = fmaf(vv, we.z, ae[i][2]);
                    ae[i][3] = fmaf(vv, we.w, ae[i][3]);
                    aa[i][0] = fmaf(vv, wa.x, aa[i][0]);
                    aa[i][1] = fmaf(vv, wa.y, aa[i][1]);
                    aa[i][2] = fmaf(vv, wa.z, aa[i][2]);
                    aa[i][3] = fmaf(vv, wa.w, aa[i][3]);
                }
            }
        }
        float4 eb = *(const float4*)&e_b[c0];
        float4 ab = *(const float4*)&a_b[c0];
        #pragma unroll
        for (int i = 0; i < 4; i++) {
            int row = row0 + r0 + i;
            float4 oe, oa;
            oe.x = fsigmoid(ae[i][0] + eb.x); oe.y = fsigmoid(ae[i][1] + eb.y);
            oe.z = fsigmoid(ae[i][2] + eb.z); oe.w = fsigmoid(ae[i][3] + eb.w);
            oa.x = ftanh(aa[i][0] + ab.x);    oa.y = ftanh(aa[i][1] + ab.y);
            oa.z = ftanh(aa[i][2] + ab.z);    oa.w = ftanh(aa[i][3] + ab.w);
            *(float4*)&g_e[(size_t)row*D_ + c0] = oe;
            *(float4*)&g_a[(size_t)row*D_ + c0] = oa;
        }
    }
}

// =====================================================================
// Kernel 2: sequential scan over t; grid (B, 2 d-halves) x 256 threads
// thread = (mg in 0..3 low bits, dl in 0..63); Mv column slice in registers
// =====================================================================
extern "C" __global__ void __launch_bounds__(256)
k2_scan(const float* __restrict__ Mv0)
{
    const int b   = blockIdx.x;
    const int tid = threadIdx.x;
    const int mg  = tid & 3;
    const int dl  = tid >> 2;
    const int d   = blockIdx.y * 64 + dl;
    const int mbase = mg * 16;

    float mv[16];
    #pragma unroll
    for (int i = 0; i < 16; i++) {
        int m = mbase + i;
        mv[i] = (m < M_) ? Mv0[m*D_ + d] : 0.f;
    }

    const float* ep = g_e + (size_t)b*L_*D_ + d;
    const float* ap = g_a + (size_t)b*L_*D_ + d;
    const float* wbase = g_w + (size_t)b*L_*WSTR + mbase;
    float* rp = g_read + (size_t)b*L_*D_ + d;

    float ev = __ldg(ep);
    float av = __ldg(ap);
    float4 w4[4];
    #pragma unroll
    for (int j = 0; j < 4; j++) w4[j] = __ldg((const float4*)wbase + j);

    for (int t = 0; t < L_; t++) {
        // prefetch t+1 (independent of mv chain)
        float ev_n = 0.f, av_n = 0.f;
        float4 wn[4] = {};
        if (t + 1 < L_) {
            ev_n = __ldg(ep + (t+1)*D_);
            av_n = __ldg(ap + (t+1)*D_);
            const float4* wq = (const float4*)(wbase + (t+1)*WSTR);
            #pragma unroll
            for (int j = 0; j < 4; j++) wn[j] = __ldg(wq + j);
        }

        float rd = 0.f;
        #pragma unroll
        for (int j = 0; j < 4; j++) {
            float wv[4] = {w4[j].x, w4[j].y, w4[j].z, w4[j].w};
            #pragma unroll
            for (int s = 0; s < 4; s++) {
                int i = j*4 + s;
                float w = wv[s];
                rd = fmaf(w, mv[i], rd);            // read uses PRE-update Mv
                float g = fmaf(-ev, mv[i], av);     // a - e*mv
                mv[i] = fmaf(w, g, mv[i]);          // mv += w*(a - e*mv)
            }
        }
        rd += __shfl_xor_sync(0xffffffffu, rd, 1);
        rd += __shfl_xor_sync(0xffffffffu, rd, 2);
        if (mg == 0) rp[t*D_] = rd;

        ev = ev_n; av = av_n;
        #pragma unroll
        for (int j = 0; j < 4; j++) w4[j] = wn[j];
    }
}

// =====================================================================
// Kernel 3: f = tanh([read,k] @ f_W^T + f_b); p = sigmoid(f·p_W + p_b)
// 400 blocks x 256 threads, 32 rows/block
// =====================================================================
extern "C" __global__ void __launch_bounds__(256)
k3_out(const int* __restrict__ skills, const float* __restrict__ k_emb,
       const float* __restrict__ f_W, const float* __restrict__ f_b,
       const float* __restrict__ p_W, const float* __restrict__ p_b,
       float* __restrict__ out)
{
    extern __shared__ float sm[];
    float* fWT = sm;                 // 256*132
    float* hx  = fWT + 2*D_*132;     // 32*256
    __shared__ int s_sk[ROWS];

    const int tid  = threadIdx.x;
    const int row0 = blockIdx.x * ROWS;

    if (tid < ROWS) s_sk[tid] = skills[row0 + tid];
    for (int i = tid; i < D_*2*D_; i += 256) {   // 32768
        int dd = i >> 8, j = i & 255;
        fWT[j*132 + dd] = f_W[i];
    }
    __syncthreads();
    {
        float4* h4 = (float4*)hx;
        const float4* rd4 = (const float4*)g_read;
        const float4* ke4 = (const float4*)k_emb;
        for (int u = tid; u < ROWS*64; u += 256) {
            int r = u >> 6, c = u & 63;
            float4 val = (c < 32) ? rd4[(size_t)(row0 + r)*32 + c]
                                  : ke4[s_sk[r]*32 + (c - 32)];
            h4[r*64 + c] = val;
        }
    }
    __syncthreads();

    const int tx = tid & 31, ty = tid >> 5;
    const int r0 = ty * 4, c0 = tx * 4;

    float acc[4][4] = {};
    const float4* h4 = (const float4*)hx;
    #pragma unroll 4
    for (int k4 = 0; k4 < 64; k4++) {
        float4 hr[4];
        #pragma unroll
        for (int i = 0; i < 4; i++) hr[i] = h4[(r0+i)*64 + k4];
        #pragma unroll
        for (int s = 0; s < 4; s++) {
            int k = k4*4 + s;
            float4 w = *(const float4*)&fWT[k*132 + c0];
            #pragma unroll
            for (int i = 0; i < 4; i++) {
                float hv = ((float*)&hr[i])[s];
                acc[i][0] = fmaf(hv, w.x, acc[i][0]);
                acc[i][1] = fmaf(hv, w.y, acc[i][1]);
                acc[i][2] = fmaf(hv, w.z, acc[i][2]);
                acc[i][3] = fmaf(hv, w.w, acc[i][3]);
            }
        }
    }
    float4 fb = *(const float4*)&f_b[c0];
    float4 pw = *(const float4*)&p_W[c0];
    float pb = p_b[0];
    #pragma unroll
    for (int i = 0; i < 4; i++) {
        float f0 = ftanh(acc[i][0] + fb.x);
        float f1 = ftanh(acc[i][1] + fb.y);
        float f2 = ftanh(acc[i][2] + fb.z);
        float f3 = ftanh(acc[i][3] + fb.w);
        float pp = f0*pw.x + f1*pw.y + f2*pw.z + f3*pw.w;
        #pragma unroll
        for (int o = 16; o >= 1; o >>= 1) pp += __shfl_xor_sync(0xffffffffu, pp, o);
        if (tx == 0) {
            int row = row0 + r0 + i;
            int b = row / L_, t = row % L_;
            if (t >= 1) out[b*(L_-1) + (t-1)] = fsigmoid(pp + pb);
        }
    }
}

// =====================================================================
extern "C" void kernel_launch(void* const* d_in, const int* in_sizes, int n_in,
                              void* d_out, int out_size)
{
    const int*   skills    = (const int*)  d_in[0];
    const int*   responses = (const int*)  d_in[1];
    const float* k_emb     = (const float*)d_in[2];
    const float* v_emb     = (const float*)d_in[3];
    const float* Mk        = (const float*)d_in[4];
    const float* Mv0       = (const float*)d_in[5];
    const float* e_W       = (const float*)d_in[6];
    const float* e_b       = (const float*)d_in[7];
    const float* a_W       = (const float*)d_in[8];
    const float* a_b       = (const float*)d_in[9];
    const float* f_W       = (const float*)d_in[10];
    const float* f_b       = (const float*)d_in[11];
    const float* p_W       = (const float*)d_in[12];
    const float* p_b       = (const float*)d_in[13];
    float* out = (float*)d_out;

    const size_t SZ1 = (size_t)(ROWS*D_*2 + D_*65 + 2*D_*132) * sizeof(float);   // 201216
    const size_t SZ3 = (size_t)(2*D_*132 + ROWS*2*D_) * sizeof(float);           // 167936

    cudaFuncSetAttribute(k1_precompute, cudaFuncAttributeMaxDynamicSharedMemorySize, (int)SZ1);
    cudaFuncSetAttribute(k3_out,        cudaFuncAttributeMaxDynamicSharedMemorySize, (int)SZ3);

    k1_precompute<<<BL_/ROWS, 256, SZ1>>>(skills, responses, k_emb, v_emb, Mk,
                                          e_W, e_b, a_W, a_b);
    k2_scan<<<dim3(B_, 2), 256>>>(Mv0);
    k3_out<<<BL_/ROWS, 256, SZ3>>>(skills, k_emb, f_W, f_b, p_W, p_b, out);
}

// round 2
// speedup vs baseline: 1.5886x; 1.5886x over previous
#include <cuda_runtime.h>

#define B_  64
#define L_  200
#define NS_ 1000
#define D_  128
#define M_  50
#define BL_ (B_*L_)
#define WSTR 64   // padded w-row stride (slots 50..63 zero)

// -------- scratch (device globals; no allocation allowed) --------
__device__ float g_wtab[1024*WSTR];   // softmax weights per skill (padded)
__device__ float g_etab[2016*D_];     // sigmoid erase per x
__device__ float g_atab[2016*D_];     // tanh add per x
__device__ float g_kftab[1024*D_];    // k_emb[s] @ f_Wk^T (no bias/act)
__device__ float g_read[BL_*D_];      // read vectors

__device__ __forceinline__ float fsigmoid(float x){ return 1.f/(1.f+__expf(-x)); }
__device__ __forceinline__ float ftanh(float x){ float y; asm("tanh.approx.f32 %0, %1;":"=f"(y):"f"(x)); return y; }

// =====================================================================
// Kernel A: build all tables.
//   blocks 0..62  : e/a tables over 2016 (>=2000) v_emb rows, 32 rows/block
//   blocks 63..94 : w (softmax) + kf tables over 1024 (>=1000) k_emb rows
// 256 threads. smem (dynamic): max(4096+2*16896, 4096+8320+16896) floats
// =====================================================================
extern "C" __global__ void __launch_bounds__(256)
kA_tables(const float* __restrict__ k_emb, const float* __restrict__ v_emb,
          const float* __restrict__ Mk,
          const float* __restrict__ e_W, const float* __restrict__ e_b,
          const float* __restrict__ a_W, const float* __restrict__ a_b,
          const float* __restrict__ f_W)
{
    extern __shared__ float sm[];
    const int tid = threadIdx.x;
    const int tx = tid & 31, ty = tid >> 5;
    const int rr0 = ty * 4, c0 = tx * 4;

    if (blockIdx.x < 63) {
        // ---------------- e/a tables ----------------
        float* vx  = sm;               // 32*128
        float* eWT = vx  + 32*D_;      // 128*132
        float* aWT = eWT + D_*132;     // 128*132
        const int r0 = blockIdx.x * 32;

        for (int i = tid; i < D_*D_; i += 256) {
            int d = i >> 7, k = i & 127;
            eWT[k*132 + d] = e_W[i];
            aWT[k*132 + d] = a_W[i];
        }
        {
            float4* vx4 = (float4*)vx;
            const float4* ve4 = (const float4*)v_emb;
            for (int u = tid; u < 32*32; u += 256) {
                int r = u >> 5, c = u & 31;
                int rr = min(r0 + r, 2*NS_ - 1);
                vx4[r*32 + c] = ve4[rr*32 + c];
            }
        }
        __syncthreads();

        float ae[4][4] = {}, aa[4][4] = {};
        const float4* vx4 = (const float4*)vx;
        #pragma unroll 4
        for (int k4 = 0; k4 < 32; k4++) {
            float4 vr[4];
            #pragma unroll
            for (int i = 0; i < 4; i++) vr[i] = vx4[(rr0+i)*32 + k4];
            #pragma unroll
            for (int s = 0; s < 4; s++) {
                int k = 4*k4 + s;
                float4 we = *(const float4*)&eWT[k*132 + c0];
                float4 wa = *(const float4*)&aWT[k*132 + c0];
                #pragma unroll
                for (int i = 0; i < 4; i++) {
                    float vv = ((float*)&vr[i])[s];
                    ae[i][0] = fmaf(vv, we.x, ae[i][0]);
                    ae[i][1] = fmaf(vv, we.y, ae[i][1]);
                    ae[i][2] = fmaf(vv, we.z, ae[i][2]);
                    ae[i][3] = fmaf(vv, we.w, ae[i][3]);
                    aa[i][0] = fmaf(vv, wa.x, aa[i][0]);
                    aa[i][1] = fmaf(vv, wa.y, aa[i][1]);
                    aa[i][2] = fmaf(vv, wa.z, aa[i][2]);
                    aa[i][3] = fmaf(vv, wa.w, aa[i][3]);
                }
            }
        }
        float4 eb = *(const float4*)&e_b[c0];
        float4 ab = *(const float4*)&a_b[c0];
        #pragma unroll
        for (int i = 0; i < 4; i++) {
            int row = r0 + rr0 + i;
            float4 oe, oa;
            oe.x = fsigmoid(ae[i][0] + eb.x); oe.y = fsigmoid(ae[i][1] + eb.y);
            oe.z = fsigmoid(ae[i][2] + eb.z); oe.w = fsigmoid(ae[i][3] + eb.w);
            oa.x = ftanh(aa[i][0] + ab.x);    oa.y = ftanh(aa[i][1] + ab.y);
            oa.z = ftanh(aa[i][2] + ab.z);    oa.w = ftanh(aa[i][3] + ab.w);
            *(float4*)&g_etab[(size_t)row*D_ + c0] = oe;
            *(float4*)&g_atab[(size_t)row*D_ + c0] = oa;
        }
    } else {
        // ---------------- w + kf tables ----------------
        float* kx  = sm;               // 32*128
        float* MkT = kx  + 32*D_;      // 128*65
        float* fkT = MkT + D_*65;      // 128*132
        const int r0 = (blockIdx.x - 63) * 32;

        for (int i = tid; i < M_*D_; i += 256) {
            int m = i >> 7, k = i & 127;
            MkT[k*65 + m] = Mk[i];
        }
        for (int i = tid; i < D_*14; i += 256) {
            int k = i / 14, m = 50 + (i % 14);
            MkT[k*65 + m] = 0.f;
        }
        for (int i = tid; i < D_*D_; i += 256) {
            int d = i >> 7, k = i & 127;
            fkT[k*132 + d] = f_W[d*(2*D_) + D_ + k];   // k-half of f_W
        }
        {
            float4* kx4 = (float4*)kx;
            const float4* ke4 = (const float4*)k_emb;
            for (int u = tid; u < 32*32; u += 256) {
                int r = u >> 5, c = u & 31;
                int rr = min(r0 + r, NS_ - 1);
                kx4[r*32 + c] = ke4[rr*32 + c];
            }
        }
        __syncthreads();

        // logits + softmax -> g_wtab
        {
            const int m0 = tx, m1 = tx + 32;
            float acc[4][2] = {};
            const float4* kx4 = (const float4*)kx;
            #pragma unroll 4
            for (int k4 = 0; k4 < 32; k4++) {
                float4 kr[4];
                #pragma unroll
                for (int i = 0; i < 4; i++) kr[i] = kx4[(rr0+i)*32 + k4];
                #pragma unroll
                for (int s = 0; s < 4; s++) {
                    int k = 4*k4 + s;
                    float mv0 = MkT[k*65 + m0];
                    float mv1 = MkT[k*65 + m1];
                    #pragma unroll
                    for (int i = 0; i < 4; i++) {
                        float kv = ((float*)&kr[i])[s];
                        acc[i][0] = fmaf(kv, mv0, acc[i][0]);
                        acc[i][1] = fmaf(kv, mv1, acc[i][1]);
                    }
                }
            }
            #pragma unroll
            for (int i = 0; i < 4; i++) {
                float v0 = acc[i][0];
                float v1 = (m1 < M_) ? acc[i][1] : -1e30f;
                float mx = fmaxf(v0, v1);
                #pragma unroll
                for (int o = 16; o >= 1; o >>= 1) mx = fmaxf(mx, __shfl_xor_sync(0xffffffffu, mx, o));
                float e0 = __expf(v0 - mx);
                float e1 = (m1 < M_) ? __expf(v1 - mx) : 0.f;
                float s = e0 + e1;
                #pragma unroll
                for (int o = 16; o >= 1; o >>= 1) s += __shfl_xor_sync(0xffffffffu, s, o);
                float inv = __frcp_rn(s);
                int row = r0 + rr0 + i;
                g_wtab[row*WSTR + m0] = e0 * inv;
                g_wtab[row*WSTR + m1] = e1 * inv;   // zero in pad region
            }
        }

        // kf GEMM -> g_kftab (no bias / activation here)
        {
            float acc[4][4] = {};
            const float4* kx4 = (const float4*)kx;
            #pragma unroll 4
            for (int k4 = 0; k4 < 32; k4++) {
                float4 kr[4];
                #pragma unroll
                for (int i = 0; i < 4; i++) kr[i] = kx4[(rr0+i)*32 + k4];
                #pragma unroll
                for (int s = 0; s < 4; s++) {
                    int k = 4*k4 + s;
                    float4 w = *(const float4*)&fkT[k*132 + c0];
                    #pragma unroll
                    for (int i = 0; i < 4; i++) {
                        float kv = ((float*)&kr[i])[s];
                        acc[i][0] = fmaf(kv, w.x, acc[i][0]);
                        acc[i][1] = fmaf(kv, w.y, acc[i][1]);
                        acc[i][2] = fmaf(kv, w.z, acc[i][2]);
                        acc[i][3] = fmaf(kv, w.w, acc[i][3]);
                    }
                }
            }
            #pragma unroll
            for (int i = 0; i < 4; i++) {
                int row = r0 + rr0 + i;
                float4 o;
                o.x = acc[i][0]; o.y = acc[i][1]; o.z = acc[i][2]; o.w = acc[i][3];
                *(float4*)&g_kftab[(size_t)row*D_ + c0] = o;
            }
        }
    }
}

// =====================================================================
// Kernel B: sequential scan; grid (B, 2 d-halves) x 256 threads.
// Gathers w/e/a from tables via indices staged in smem; Mv in registers.
// =====================================================================
extern "C" __global__ void __launch_bounds__(256)
kB_scan(const int* __restrict__ skills, const int* __restrict__ responses,
        const float* __restrict__ Mv0)
{
    __shared__ int s_sk[L_], s_x[L_];
    const int b   = blockIdx.x;
    const int tid = threadIdx.x;

    for (int t = tid; t < L_; t += 256) {
        int sk = skills[b*L_ + t];
        int r  = responses[b*L_ + t];
        int mr = (r > -1) ? r : 0;
        s_sk[t] = sk;
        s_x[t]  = sk + NS_ * mr;
    }
    __syncthreads();

    const int mg  = tid & 3;
    const int dl  = tid >> 2;
    const int d   = blockIdx.y * 64 + dl;
    const int mbase = mg * 16;

    float mv[16];
    #pragma unroll
    for (int i = 0; i < 16; i++) {
        int m = mbase + i;
        mv[i] = (m < M_) ? Mv0[m*D_ + d] : 0.f;
    }

    float* rp = g_read + (size_t)b*L_*D_ + d;

    float ev, av; float4 w4[4];
    {
        int xx = s_x[0], kk = s_sk[0];
        ev = __ldg(&g_etab[(size_t)xx*D_ + d]);
        av = __ldg(&g_atab[(size_t)xx*D_ + d]);
        const float4* wq = (const float4*)(g_wtab + kk*WSTR + mbase);
        #pragma unroll
        for (int j = 0; j < 4; j++) w4[j] = __ldg(wq + j);
    }

    for (int t = 0; t < L_; t++) {
        float ev_n = 0.f, av_n = 0.f;
        float4 wn[4] = {};
        if (t + 1 < L_) {
            int xx = s_x[t+1], kk = s_sk[t+1];
            ev_n = __ldg(&g_etab[(size_t)xx*D_ + d]);
            av_n = __ldg(&g_atab[(size_t)xx*D_ + d]);
            const float4* wq = (const float4*)(g_wtab + kk*WSTR + mbase);
            #pragma unroll
            for (int j = 0; j < 4; j++) wn[j] = __ldg(wq + j);
        }

        float rda[4] = {0.f, 0.f, 0.f, 0.f};   // 4 accumulators: break serial chain
        #pragma unroll
        for (int j = 0; j < 4; j++) {
            float wv[4] = {w4[j].x, w4[j].y, w4[j].z, w4[j].w};
            #pragma unroll
            for (int s = 0; s < 4; s++) {
                int i = j*4 + s;
                float w = wv[s];
                rda[j] = fmaf(w, mv[i], rda[j]);   // read uses PRE-update Mv
                float g = fmaf(-ev, mv[i], av);    // a - e*mv
                mv[i] = fmaf(w, g, mv[i]);         // mv += w*(a - e*mv)
            }
        }
        float rd = (rda[0] + rda[1]) + (rda[2] + rda[3]);
        rd += __shfl_xor_sync(0xffffffffu, rd, 1);
        rd += __shfl_xor_sync(0xffffffffu, rd, 2);
        if (mg == 0) rp[t*D_] = rd;

        ev = ev_n; av = av_n;
        #pragma unroll
        for (int j = 0; j < 4; j++) w4[j] = wn[j];
    }
}

// =====================================================================
// Kernel C: f = tanh(read @ f_Wr^T + kf_tab[skill] + f_b); p = sigmoid(f.p_W+p_b)
// 400 blocks x 256 threads, 32 rows/block; 84KB smem -> 2 blocks/SM
// =====================================================================
extern "C" __global__ void __launch_bounds__(256, 2)
kC_out(const int* __restrict__ skills,
       const float* __restrict__ f_W, const float* __restrict__ f_b,
       const float* __restrict__ p_W, const float* __restrict__ p_b,
       float* __restrict__ out)
{
    extern __shared__ float sm[];
    float* fWT = sm;                 // 128*132 (read-half of f_W, transposed)
    float* hx  = fWT + D_*132;       // 32*128
    __shared__ int s_sk[32];

    const int tid  = threadIdx.x;
    const int row0 = blockIdx.x * 32;

    if (tid < 32) s_sk[tid] = skills[row0 + tid];
    for (int i = tid; i < D_*D_; i += 256) {
        int d = i >> 7, k = i & 127;
        fWT[k*132 + d] = f_W[d*(2*D_) + k];   // read-half columns
    }
    {
        float4* h4 = (float4*)hx;
        const float4* rd4 = (const float4*)g_read;
        for (int u = tid; u < 32*32; u += 256) {
            int r = u >> 5, c = u & 31;
            h4[r*32 + c] = rd4[(size_t)(row0 + r)*32 + c];
        }
    }
    __syncthreads();

    const int tx = tid & 31, ty = tid >> 5;
    const int r0 = ty * 4, c0 = tx * 4;

    float acc[4][4] = {};
    const float4* h4 = (const float4*)hx;
    #pragma unroll 4
    for (int k4 = 0; k4 < 32; k4++) {
        float4 hr[4];
        #pragma unroll
        for (int i = 0; i < 4; i++) hr[i] = h4[(r0+i)*32 + k4];
        #pragma unroll
        for (int s = 0; s < 4; s++) {
            int k = k4*4 + s;
            float4 w = *(const float4*)&fWT[k*132 + c0];
            #pragma unroll
            for (int i = 0; i < 4; i++) {
                float hv = ((float*)&hr[i])[s];
                acc[i][0] = fmaf(hv, w.x, acc[i][0]);
                acc[i][1] = fmaf(hv, w.y, acc[i][1]);
                acc[i][2] = fmaf(hv, w.z, acc[i][2]);
                acc[i][3] = fmaf(hv, w.w, acc[i][3]);
            }
        }
    }
    float4 fb = *(const float4*)&f_b[c0];
    float4 pw = *(const float4*)&p_W[c0];
    float pb = p_b[0];
    #pragma unroll
    for (int i = 0; i < 4; i++) {
        int row = row0 + r0 + i;
        int sk = s_sk[r0 + i];
        float4 kf = *(const float4*)&g_kftab[(size_t)sk*D_ + c0];
        float f0 = ftanh(acc[i][0] + kf.x + fb.x);
        float f1 = ftanh(acc[i][1] + kf.y + fb.y);
        float f2 = ftanh(acc[i][2] + kf.z + fb.z);
        float f3 = ftanh(acc[i][3] + kf.w + fb.w);
        float pp = f0*pw.x + f1*pw.y + f2*pw.z + f3*pw.w;
        #pragma unroll
        for (int o = 16; o >= 1; o >>= 1) pp += __shfl_xor_sync(0xffffffffu, pp, o);
        if (tx == 0) {
            int bb = row / L_, t = row % L_;
            if (t >= 1) out[bb*(L_-1) + (t-1)] = fsigmoid(pp + pb);
        }
    }
}

// =====================================================================
extern "C" void kernel_launch(void* const* d_in, const int* in_sizes, int n_in,
                              void* d_out, int out_size)
{
    const int*   skills    = (const int*)  d_in[0];
    const int*   responses = (const int*)  d_in[1];
    const float* k_emb     = (const float*)d_in[2];
    const float* v_emb     = (const float*)d_in[3];
    const float* Mk        = (const float*)d_in[4];
    const float* Mv0       = (const float*)d_in[5];
    const float* e_W       = (const float*)d_in[6];
    const float* e_b       = (const float*)d_in[7];
    const float* a_W       = (const float*)d_in[8];
    const float* a_b       = (const float*)d_in[9];
    const float* f_W       = (const float*)d_in[10];
    const float* f_b       = (const float*)d_in[11];
    const float* p_W       = (const float*)d_in[12];
    const float* p_b       = (const float*)d_in[13];
    float* out = (float*)d_out;

    const size_t SZA = (size_t)(32*D_ + 2*D_*132) * sizeof(float);   // 151552
    const size_t SZC = (size_t)(D_*132 + 32*D_) * sizeof(float);     //  83968

    cudaFuncSetAttribute(kA_tables, cudaFuncAttributeMaxDynamicSharedMemorySize, (int)SZA);
    cudaFuncSetAttribute(kC_out,    cudaFuncAttributeMaxDynamicSharedMemorySize, (int)SZC);

    kA_tables<<<95, 256, SZA>>>(k_emb, v_emb, Mk, e_W, e_b, a_W, a_b, f_W);
    kB_scan<<<dim3(B_, 2), 256>>>(skills, responses, Mv0);
    kC_out<<<BL_/32, 256, SZC>>>(skills, f_W, f_b, p_W, p_b, out);
}